// round 3
// baseline (speedup 1.0000x reference)
#include <cuda_runtime.h>
#include <math.h>

// Problem constants
#define BATCH 8
#define CCH   512
#define NTOK  1024

// Scratch buffers (device globals — no allocation allowed)
__device__ float g_hn[BATCH * CCH * NTOK];        // GroupNorm1 output
__device__ float g_qkv[BATCH * 3 * CCH * NTOK];   // qkv conv output
__device__ float g_attn[BATCH * CCH * NTOK];      // attention output
__device__ float g_proj[BATCH * CCH * NTOK];      // proj conv output

// ---------------------------------------------------------------------------
// GroupNorm over 32 groups of 16 channels x 1024 spatial (contiguous 16384
// floats per (b,g)). One block per (b,g). Optional residual add (for GN2).
// ---------------------------------------------------------------------------
template <bool ADD_RES>
__global__ __launch_bounds__(256)
void gn_kernel(const float* __restrict__ x,
               const float* __restrict__ scale,
               const float* __restrict__ bias,
               const float* __restrict__ resid,
               float* __restrict__ out) {
    __shared__ float s_sum[256];
    __shared__ float s_sq[256];
    int blk = blockIdx.x;           // b*32 + g
    int g = blk & 31;
    size_t base = (size_t)blk * 16 * 1024;
    int tid = threadIdx.x;

    float sum = 0.f, sq = 0.f;
    for (int i = tid; i < 16384; i += 256) {
        float v = x[base + i];
        sum += v;
        sq += v * v;
    }
    s_sum[tid] = sum;
    s_sq[tid] = sq;
    __syncthreads();
    for (int off = 128; off; off >>= 1) {
        if (tid < off) {
            s_sum[tid] += s_sum[tid + off];
            s_sq[tid] += s_sq[tid + off];
        }
        __syncthreads();
    }
    float mean = s_sum[0] * (1.0f / 16384.0f);
    float var = s_sq[0] * (1.0f / 16384.0f) - mean * mean;
    float rstd = rsqrtf(var + 1e-5f);

    for (int i = tid; i < 16384; i += 256) {
        int c = g * 16 + (i >> 10);
        float v = (x[base + i] - mean) * rstd * scale[c] + bias[c];
        out[base + i] = ADD_RES ? resid[base + i] + v : v;
    }
}

// ---------------------------------------------------------------------------
// Batched GEMM + bias: C[z][m][n] = sum_k A[m][k] * B[z][k][n] + bias[m]
// A shared across batches (1x1 conv weight). 64x64 block tile, BK=16,
// 256 threads, 4x4 micro-tile per thread. All dims divide tiles exactly.
// ---------------------------------------------------------------------------
__global__ __launch_bounds__(256)
void gemm_bias_kernel(const float* __restrict__ A,
                      const float* __restrict__ Bm,
                      const float* __restrict__ bias,
                      float* __restrict__ Cm,
                      int M, int N, int K) {
    __shared__ float As[16][68];  // [k][m], padded
    __shared__ float Bs[16][68];  // [k][n], padded

    const float* B = Bm + (size_t)blockIdx.z * K * N;
    float* Cp = Cm + (size_t)blockIdx.z * M * N;
    int m0 = blockIdx.y * 64;
    int n0 = blockIdx.x * 64;
    int tid = threadIdx.x;
    int ty = tid >> 4;   // 0..15 (m direction)
    int tx = tid & 15;   // 0..15 (n direction)

    float acc[4][4] = {};

    for (int k0 = 0; k0 < K; k0 += 16) {
#pragma unroll
        for (int it = 0; it < 4; it++) {
            int i = tid + it * 256;
            int m = i >> 4, k = i & 15;
            As[k][m] = A[(size_t)(m0 + m) * K + k0 + k];
        }
#pragma unroll
        for (int it = 0; it < 4; it++) {
            int i = tid + it * 256;
            int k = i >> 6, n = i & 63;
            Bs[k][n] = B[(size_t)(k0 + k) * N + n0 + n];
        }
        __syncthreads();
#pragma unroll
        for (int k = 0; k < 16; k++) {
            float4 a4 = *(const float4*)&As[k][ty * 4];
            float4 b4 = *(const float4*)&Bs[k][tx * 4];
            float av[4] = {a4.x, a4.y, a4.z, a4.w};
            float bv[4] = {b4.x, b4.y, b4.z, b4.w};
#pragma unroll
            for (int i = 0; i < 4; i++)
#pragma unroll
                for (int j = 0; j < 4; j++)
                    acc[i][j] += av[i] * bv[j];
        }
        __syncthreads();
    }

#pragma unroll
    for (int i = 0; i < 4; i++) {
        float bi = bias[m0 + ty * 4 + i];
        float4 o = make_float4(acc[i][0] + bi, acc[i][1] + bi,
                               acc[i][2] + bi, acc[i][3] + bi);
        *(float4*)&Cp[(size_t)(m0 + ty * 4 + i) * N + n0 + tx * 4] = o;
    }
}

// ---------------------------------------------------------------------------
// Flash-style attention per (batch*head, 64-row t-tile). STATIC smem <=48KB.
// q,k,v slices of qkv: channel offsets h*192 + {0,64,128}.
// scale^2 = 64^-0.5 = 1/8 folded into q. Online softmax over s-tiles of 32.
// Thread map: 16x16 grid; t microtile 4 (ty), s microtile 2 / c microtile 4 (tx).
// ---------------------------------------------------------------------------
__global__ __launch_bounds__(256)
void attn_kernel(const float* __restrict__ qkv,
                 float* __restrict__ aout) {
    __shared__ float qs[64][68];   // [c][t]   17408 B
    __shared__ float ks[64][36];   // [c][s]    9216 B
    __shared__ float vsT[32][68];  // [s][c]    8704 B
    __shared__ float Ps[64][36];   // [t][s]    9216 B   total 44544 B

    int bh = blockIdx.y;
    int t0 = blockIdx.x * 64;
    int b = bh >> 3, h = bh & 7;
    const float* base = qkv + ((size_t)b * 1536 + h * 192) * 1024;
    int tid = threadIdx.x;
    int ty = tid >> 4;  // 0..15: t direction (4 rows each)
    int tx = tid & 15;  // 0..15: s (2 each) / c (4 each)

    // Load q tile once, folding in scale^2 = 0.125
#pragma unroll
    for (int it = 0; it < 16; it++) {
        int i = tid + it * 256;
        int c = i >> 6, t = i & 63;
        qs[c][t] = base[c * 1024 + t0 + t] * 0.125f;
    }

    float mrow[4] = {-INFINITY, -INFINITY, -INFINITY, -INFINITY};
    float lrow[4] = {0.f, 0.f, 0.f, 0.f};
    float O[4][4] = {};
    __syncthreads();

    for (int s0 = 0; s0 < 1024; s0 += 32) {
        // Load K tile [c][s] (64x32) and V tile transposed [s][c] (32x64)
#pragma unroll
        for (int it = 0; it < 8; it++) {
            int i = tid + it * 256;
            int c = i >> 5, s = i & 31;
            ks[c][s] = base[(64 + c) * 1024 + s0 + s];
        }
#pragma unroll
        for (int it = 0; it < 8; it++) {
            int i = tid + it * 256;
            int s = i >> 6, c = i & 63;
            vsT[s][c] = base[(128 + c) * 1024 + s0 + s];
        }
        __syncthreads();

        // S[t][s] = sum_c q[c][t] * k[c][s]   (4 t-rows x 2 s-cols per thread)
        float S[4][2] = {};
#pragma unroll 16
        for (int c = 0; c < 64; c++) {
            float4 qa = *(const float4*)&qs[c][ty * 4];
            float2 kb = *(const float2*)&ks[c][tx * 2];
            float av[4] = {qa.x, qa.y, qa.z, qa.w};
#pragma unroll
            for (int i = 0; i < 4; i++) {
                S[i][0] += av[i] * kb.x;
                S[i][1] += av[i] * kb.y;
            }
        }

        // Online softmax per row (row group = 16 consecutive lanes spans s-tile)
#pragma unroll
        for (int i = 0; i < 4; i++) {
            float rmax = fmaxf(S[i][0], S[i][1]);
#pragma unroll
            for (int o = 1; o < 16; o <<= 1)
                rmax = fmaxf(rmax, __shfl_xor_sync(0xffffffffu, rmax, o));
            float mn = fmaxf(mrow[i], rmax);
            float corr = expf(mrow[i] - mn);
            float p0 = expf(S[i][0] - mn);
            float p1 = expf(S[i][1] - mn);
            float psum = p0 + p1;
#pragma unroll
            for (int o = 1; o < 16; o <<= 1)
                psum += __shfl_xor_sync(0xffffffffu, psum, o);
            lrow[i] = lrow[i] * corr + psum;
            mrow[i] = mn;
#pragma unroll
            for (int j = 0; j < 4; j++) O[i][j] *= corr;
            *(float2*)&Ps[ty * 4 + i][tx * 2] = make_float2(p0, p1);
        }
        __syncthreads();

        // O[t][c] += sum_s P[t][s] * v[c][s]
#pragma unroll 8
        for (int s = 0; s < 32; s++) {
            float4 vb = *(const float4*)&vsT[s][tx * 4];
            float bv[4] = {vb.x, vb.y, vb.z, vb.w};
#pragma unroll
            for (int i = 0; i < 4; i++) {
                float p = Ps[ty * 4 + i][s];
#pragma unroll
                for (int j = 0; j < 4; j++)
                    O[i][j] += p * bv[j];
            }
        }
        __syncthreads();
    }

    // Epilogue: normalize and write a[b][h*64 + c][t]
    size_t obase = ((size_t)b * 512 + h * 64) * 1024 + t0;
#pragma unroll
    for (int i = 0; i < 4; i++) {
        float inv = 1.0f / lrow[i];
#pragma unroll
        for (int j = 0; j < 4; j++)
            aout[obase + (size_t)(tx * 4 + j) * 1024 + ty * 4 + i] = O[i][j] * inv;
    }
}

// ---------------------------------------------------------------------------
// Launch
// ---------------------------------------------------------------------------
extern "C" void kernel_launch(void* const* d_in, const int* in_sizes, int n_in,
                              void* d_out, int out_size) {
    const float* x      = (const float*)d_in[0];
    const float* gn1_s  = (const float*)d_in[1];
    const float* gn1_b  = (const float*)d_in[2];
    const float* w_qkv  = (const float*)d_in[3];
    const float* b_qkv  = (const float*)d_in[4];
    const float* w_proj = (const float*)d_in[5];
    const float* b_proj = (const float*)d_in[6];
    const float* gn2_s  = (const float*)d_in[7];
    const float* gn2_b  = (const float*)d_in[8];
    float* out = (float*)d_out;

    float *hn, *qkv, *attn, *proj;
    cudaGetSymbolAddress((void**)&hn, g_hn);
    cudaGetSymbolAddress((void**)&qkv, g_qkv);
    cudaGetSymbolAddress((void**)&attn, g_attn);
    cudaGetSymbolAddress((void**)&proj, g_proj);

    // 1) GroupNorm1
    gn_kernel<false><<<256, 256>>>(x, gn1_s, gn1_b, nullptr, hn);
    // 2) qkv = W_qkv @ hn + b  (batched: 1536 x 1024 x 512, 8 batches)
    gemm_bias_kernel<<<dim3(16, 24, 8), 256>>>(w_qkv, hn, b_qkv, qkv, 1536, 1024, 512);
    // 3) flash attention per (bh, t-tile)
    attn_kernel<<<dim3(16, 64), 256>>>(qkv, attn);
    // 4) proj = W_proj @ a + b  (512 x 1024 x 512, 8 batches)
    gemm_bias_kernel<<<dim3(16, 8, 8), 256>>>(w_proj, attn, b_proj, proj, 512, 1024, 512);
    // 5) GroupNorm2 + residual
    gn_kernel<true><<<256, 256>>>(proj, gn2_s, gn2_b, x, out);
}

// round 4
// speedup vs baseline: 1.4223x; 1.4223x over previous
#include <cuda_runtime.h>
#include <math.h>

// Problem constants
#define BATCH 8
#define CCH   512
#define NTOK  1024

// Scratch buffers (device globals — no allocation allowed)
__device__ float g_hn[BATCH * CCH * NTOK];        // GroupNorm1 output
__device__ float g_qkv[BATCH * 3 * CCH * NTOK];   // qkv conv output
__device__ float g_attn[BATCH * CCH * NTOK];      // attention output
__device__ float g_proj[BATCH * CCH * NTOK];      // proj conv output

// ---------------------------------------------------------------------------
// GroupNorm over 32 groups of 16 channels x 1024 spatial. One block per (b,g).
// ---------------------------------------------------------------------------
template <bool ADD_RES>
__global__ __launch_bounds__(256)
void gn_kernel(const float* __restrict__ x,
               const float* __restrict__ scale,
               const float* __restrict__ bias,
               const float* __restrict__ resid,
               float* __restrict__ out) {
    __shared__ float s_sum[256];
    __shared__ float s_sq[256];
    int blk = blockIdx.x;           // b*32 + g
    int g = blk & 31;
    size_t base = (size_t)blk * 16 * 1024;
    int tid = threadIdx.x;

    float sum = 0.f, sq = 0.f;
    for (int i = tid; i < 16384; i += 256) {
        float v = x[base + i];
        sum += v;
        sq += v * v;
    }
    s_sum[tid] = sum;
    s_sq[tid] = sq;
    __syncthreads();
    for (int off = 128; off; off >>= 1) {
        if (tid < off) {
            s_sum[tid] += s_sum[tid + off];
            s_sq[tid] += s_sq[tid + off];
        }
        __syncthreads();
    }
    float mean = s_sum[0] * (1.0f / 16384.0f);
    float var = s_sq[0] * (1.0f / 16384.0f) - mean * mean;
    float rstd = rsqrtf(var + 1e-5f);

    for (int i = tid; i < 16384; i += 256) {
        int c = g * 16 + (i >> 10);
        float v = (x[base + i] - mean) * rstd * scale[c] + bias[c];
        out[base + i] = ADD_RES ? resid[base + i] + v : v;
    }
}

// ---------------------------------------------------------------------------
// Batched GEMM + bias: C[z][m][n] = sum_k A[m][k] * B[z][k][n] + bias[m]
// 128x128 block tile, BK=16, 256 threads, 8x8 micro-tile (1 B LDS per
// lane-FMA -> LDS crossbar at <=50% when FMA saturates).
// ---------------------------------------------------------------------------
__global__ __launch_bounds__(256)
void gemm_bias_kernel(const float* __restrict__ A,
                      const float* __restrict__ Bm,
                      const float* __restrict__ bias,
                      float* __restrict__ Cm,
                      int M, int N, int K) {
    __shared__ float As[16][132];  // [k][m]
    __shared__ float Bs[16][132];  // [k][n]

    const float* B = Bm + (size_t)blockIdx.z * K * N;
    float* Cp = Cm + (size_t)blockIdx.z * M * N;
    int m0 = blockIdx.y * 128;
    int n0 = blockIdx.x * 128;
    int tid = threadIdx.x;
    int ty = tid >> 4;   // 0..15 (m: 8 rows each)
    int tx = tid & 15;   // 0..15 (n: 8 cols each)
    int am = tid >> 1, ak = (tid & 1) * 8;   // A-load map

    float acc[8][8] = {};

    for (int k0 = 0; k0 < K; k0 += 16) {
        // A tile (transpose to [k][m])
        float4 a0 = *(const float4*)&A[(size_t)(m0 + am) * K + k0 + ak];
        float4 a1 = *(const float4*)&A[(size_t)(m0 + am) * K + k0 + ak + 4];
        As[ak + 0][am] = a0.x; As[ak + 1][am] = a0.y;
        As[ak + 2][am] = a0.z; As[ak + 3][am] = a0.w;
        As[ak + 4][am] = a1.x; As[ak + 5][am] = a1.y;
        As[ak + 6][am] = a1.z; As[ak + 7][am] = a1.w;
        // B tile (natural [k][n])
        *(float4*)&Bs[ty][tx * 8]     = *(const float4*)&B[(size_t)(k0 + ty) * N + n0 + tx * 8];
        *(float4*)&Bs[ty][tx * 8 + 4] = *(const float4*)&B[(size_t)(k0 + ty) * N + n0 + tx * 8 + 4];
        __syncthreads();

#pragma unroll
        for (int k = 0; k < 16; k++) {
            float4 a4 = *(const float4*)&As[k][ty * 8];
            float4 a5 = *(const float4*)&As[k][ty * 8 + 4];
            float4 b4 = *(const float4*)&Bs[k][tx * 8];
            float4 b5 = *(const float4*)&Bs[k][tx * 8 + 4];
            float av[8] = {a4.x, a4.y, a4.z, a4.w, a5.x, a5.y, a5.z, a5.w};
            float bv[8] = {b4.x, b4.y, b4.z, b4.w, b5.x, b5.y, b5.z, b5.w};
#pragma unroll
            for (int i = 0; i < 8; i++)
#pragma unroll
                for (int j = 0; j < 8; j++)
                    acc[i][j] += av[i] * bv[j];
        }
        __syncthreads();
    }

#pragma unroll
    for (int i = 0; i < 8; i++) {
        float bi = bias[m0 + ty * 8 + i];
        float* crow = &Cp[(size_t)(m0 + ty * 8 + i) * N + n0 + tx * 8];
        float4 o0 = make_float4(acc[i][0] + bi, acc[i][1] + bi, acc[i][2] + bi, acc[i][3] + bi);
        float4 o1 = make_float4(acc[i][4] + bi, acc[i][5] + bi, acc[i][6] + bi, acc[i][7] + bi);
        *(float4*)crow = o0;
        *(float4*)(crow + 4) = o1;
    }
}

// ---------------------------------------------------------------------------
// Flash attention per (batch*head, 128-row t-tile). 256 threads.
// t-tile 128, s-tile 64. QK microtile 8t x 4s; PV microtile 8t x 4c.
// scale^2 = 64^-0.5 = 1/8 folded into q. Dynamic smem 103424 B.
// ---------------------------------------------------------------------------
__global__ __launch_bounds__(256)
void attn_kernel(const float* __restrict__ qkv,
                 float* __restrict__ aout) {
    extern __shared__ float sm[];
    float(*qs)[132] = (float(*)[132])sm;                          // [c=64][t=128]
    float(*ks)[68]  = (float(*)[68])(sm + 64 * 132);              // [c=64][s=64]
    float(*vsT)[68] = (float(*)[68])(sm + 64 * 132 + 64 * 68);    // [s=64][c=64]
    float(*Ps)[68]  = (float(*)[68])(sm + 64 * 132 + 2 * 64 * 68);// [t=128][s=64]

    int bh = blockIdx.y;
    int t0 = blockIdx.x * 128;
    int b = bh >> 3, h = bh & 7;
    const float* base = qkv + ((size_t)b * 1536 + h * 192) * 1024;
    int tid = threadIdx.x;
    int ty = tid >> 4;  // 0..15: t (8 rows each)
    int tx = tid & 15;  // 0..15: s (4 each) / c (4 each)

    // Load q tile [c][t] (64 x 128), folding in scale^2 = 0.125
#pragma unroll
    for (int it = 0; it < 32; it++) {
        int i = tid + it * 256;
        int c = i >> 7, t = i & 127;
        qs[c][t] = base[c * 1024 + t0 + t] * 0.125f;
    }

    float mrow[8], lrow[8];
    float O[8][4] = {};
#pragma unroll
    for (int i = 0; i < 8; i++) { mrow[i] = -INFINITY; lrow[i] = 0.f; }
    __syncthreads();

    for (int s0 = 0; s0 < 1024; s0 += 64) {
        // K tile [c][s] and V tile transposed [s][c]
#pragma unroll
        for (int it = 0; it < 16; it++) {
            int i = tid + it * 256;
            int c = i >> 6, s = i & 63;
            ks[c][s] = base[(64 + c) * 1024 + s0 + s];
        }
#pragma unroll
        for (int it = 0; it < 16; it++) {
            int i = tid + it * 256;
            int c = i >> 6, s = i & 63;
            vsT[s][c] = base[(128 + c) * 1024 + s0 + s];
        }
        __syncthreads();

        // S[t][s] = sum_c q[c][t] * k[c][s]   (8 t-rows x 4 s-cols / thread)
        float S[8][4] = {};
#pragma unroll 8
        for (int c = 0; c < 64; c++) {
            float4 qa = *(const float4*)&qs[c][ty * 8];
            float4 qb = *(const float4*)&qs[c][ty * 8 + 4];
            float4 kb = *(const float4*)&ks[c][tx * 4];
            float av[8] = {qa.x, qa.y, qa.z, qa.w, qb.x, qb.y, qb.z, qb.w};
            float bv[4] = {kb.x, kb.y, kb.z, kb.w};
#pragma unroll
            for (int i = 0; i < 8; i++)
#pragma unroll
                for (int j = 0; j < 4; j++)
                    S[i][j] += av[i] * bv[j];
        }

        // Online softmax per row (16 tx lanes span the 64-wide s-tile)
#pragma unroll
        for (int i = 0; i < 8; i++) {
            float rmax = fmaxf(fmaxf(S[i][0], S[i][1]), fmaxf(S[i][2], S[i][3]));
#pragma unroll
            for (int o = 1; o < 16; o <<= 1)
                rmax = fmaxf(rmax, __shfl_xor_sync(0xffffffffu, rmax, o));
            float mn = fmaxf(mrow[i], rmax);
            float corr = __expf(mrow[i] - mn);
            float p[4];
            float psum = 0.f;
#pragma unroll
            for (int j = 0; j < 4; j++) {
                p[j] = __expf(S[i][j] - mn);
                psum += p[j];
            }
#pragma unroll
            for (int o = 1; o < 16; o <<= 1)
                psum += __shfl_xor_sync(0xffffffffu, psum, o);
            lrow[i] = lrow[i] * corr + psum;
            mrow[i] = mn;
#pragma unroll
            for (int j = 0; j < 4; j++) O[i][j] *= corr;
            *(float4*)&Ps[ty * 8 + i][tx * 4] = make_float4(p[0], p[1], p[2], p[3]);
        }
        __syncthreads();

        // O[t][c] += sum_s P[t][s] * v[c][s]
#pragma unroll 8
        for (int s = 0; s < 64; s++) {
            float4 vb = *(const float4*)&vsT[s][tx * 4];
            float bv[4] = {vb.x, vb.y, vb.z, vb.w};
#pragma unroll
            for (int i = 0; i < 8; i++) {
                float p = Ps[ty * 8 + i][s];
#pragma unroll
                for (int j = 0; j < 4; j++)
                    O[i][j] += p * bv[j];
            }
        }
        __syncthreads();
    }

    // Epilogue: normalize, transpose through qs ([c][t]), coalesced store.
#pragma unroll
    for (int i = 0; i < 8; i++) {
        float inv = 1.0f / lrow[i];
#pragma unroll
        for (int j = 0; j < 4; j++)
            qs[tx * 4 + j][ty * 8 + i] = O[i][j] * inv;
    }
    __syncthreads();

    size_t obase = ((size_t)b * 512 + h * 64) * 1024 + t0;
#pragma unroll
    for (int it = 0; it < 8; it++) {
        int i = tid + it * 256;           // 64 rows x 32 float4
        int c = i >> 5, t4 = (i & 31) * 4;
        *(float4*)&aout[obase + (size_t)c * 1024 + t4] = *(const float4*)&qs[c][t4];
    }
}

// ---------------------------------------------------------------------------
// Launch
// ---------------------------------------------------------------------------
extern "C" void kernel_launch(void* const* d_in, const int* in_sizes, int n_in,
                              void* d_out, int out_size) {
    const float* x      = (const float*)d_in[0];
    const float* gn1_s  = (const float*)d_in[1];
    const float* gn1_b  = (const float*)d_in[2];
    const float* w_qkv  = (const float*)d_in[3];
    const float* b_qkv  = (const float*)d_in[4];
    const float* w_proj = (const float*)d_in[5];
    const float* b_proj = (const float*)d_in[6];
    const float* gn2_s  = (const float*)d_in[7];
    const float* gn2_b  = (const float*)d_in[8];
    float* out = (float*)d_out;

    float *hn, *qkv, *attn, *proj;
    cudaGetSymbolAddress((void**)&hn, g_hn);
    cudaGetSymbolAddress((void**)&qkv, g_qkv);
    cudaGetSymbolAddress((void**)&attn, g_attn);
    cudaGetSymbolAddress((void**)&proj, g_proj);

    const int ATTN_SMEM = (64 * 132 + 2 * 64 * 68 + 128 * 68) * 4;  // 103424 B
    cudaFuncSetAttribute(attn_kernel, cudaFuncAttributeMaxDynamicSharedMemorySize,
                         ATTN_SMEM);

    // 1) GroupNorm1
    gn_kernel<false><<<256, 256>>>(x, gn1_s, gn1_b, nullptr, hn);
    // 2) qkv = W_qkv @ hn + b  (batched: 1536 x 1024 x 512, 8 batches)
    gemm_bias_kernel<<<dim3(8, 12, 8), 256>>>(w_qkv, hn, b_qkv, qkv, 1536, 1024, 512);
    // 3) flash attention per (bh, 128-row t-tile)
    attn_kernel<<<dim3(8, 64), 256, ATTN_SMEM>>>(qkv, attn);
    // 4) proj = W_proj @ a + b  (512 x 1024 x 512, 8 batches)
    gemm_bias_kernel<<<dim3(8, 4, 8), 256>>>(w_proj, attn, b_proj, proj, 512, 1024, 512);
    // 5) GroupNorm2 + residual
    gn_kernel<true><<<256, 256>>>(proj, gn2_s, gn2_b, x, out);
}

// round 6
// speedup vs baseline: 2.0856x; 1.4663x over previous
#include <cuda_runtime.h>
#include <math.h>
#include <stdint.h>

// Problem constants
#define BATCH 8
#define CCH   512
#define NTOK  1024

// Scratch buffers (device globals — no allocation allowed)
__device__ float g_hn[BATCH * CCH * NTOK];        // GroupNorm1 output
__device__ float g_qkv[BATCH * 3 * CCH * NTOK];   // qkv conv output
__device__ float g_attn[BATCH * CCH * NTOK];      // attention output
__device__ float g_proj[BATCH * CCH * NTOK];      // proj conv output

// ---------------------------------------------------------------------------
// GroupNorm over 32 groups of 16 channels x 1024 spatial. One block per (b,g).
// ---------------------------------------------------------------------------
template <bool ADD_RES>
__global__ __launch_bounds__(256)
void gn_kernel(const float* __restrict__ x,
               const float* __restrict__ scale,
               const float* __restrict__ bias,
               const float* __restrict__ resid,
               float* __restrict__ out) {
    __shared__ float s_sum[256];
    __shared__ float s_sq[256];
    int blk = blockIdx.x;           // b*32 + g
    int g = blk & 31;
    size_t base = (size_t)blk * 16 * 1024;
    int tid = threadIdx.x;

    float sum = 0.f, sq = 0.f;
    for (int i = tid; i < 16384; i += 256) {
        float v = x[base + i];
        sum += v;
        sq += v * v;
    }
    s_sum[tid] = sum;
    s_sq[tid] = sq;
    __syncthreads();
    for (int off = 128; off; off >>= 1) {
        if (tid < off) {
            s_sum[tid] += s_sum[tid + off];
            s_sq[tid] += s_sq[tid + off];
        }
        __syncthreads();
    }
    float mean = s_sum[0] * (1.0f / 16384.0f);
    float var = s_sq[0] * (1.0f / 16384.0f) - mean * mean;
    float rstd = rsqrtf(var + 1e-5f);

    for (int i = tid; i < 16384; i += 256) {
        int c = g * 16 + (i >> 10);
        float v = (x[base + i] - mean) * rstd * scale[c] + bias[c];
        out[base + i] = ADD_RES ? resid[base + i] + v : v;
    }
}

// ---------------------------------------------------------------------------
// tf32 helpers
// ---------------------------------------------------------------------------
__device__ __forceinline__ float to_tf32(float x) {
    float y;
    asm("cvt.rna.tf32.f32 %0, %1;" : "=f"(y) : "f"(x));
    return y;
}

__device__ __forceinline__ void mma_tf32(float* c, const uint32_t* a, const uint32_t* b) {
    asm volatile(
        "mma.sync.aligned.m16n8k8.row.col.f32.tf32.tf32.f32 "
        "{%0,%1,%2,%3}, {%4,%5,%6,%7}, {%8,%9}, {%0,%1,%2,%3};"
        : "+f"(c[0]), "+f"(c[1]), "+f"(c[2]), "+f"(c[3])
        : "r"(a[0]), "r"(a[1]), "r"(a[2]), "r"(a[3]), "r"(b[0]), "r"(b[1]));
}

// ---------------------------------------------------------------------------
// Batched tf32 tensor-core GEMM + bias:
//   C[z][m][n] = sum_k A[m][k] * B[z][k][n] + bias[m]
// Block tile 128x128, BK=32. 8 warps (4m x 2n), warp tile 32x64.
// mma.sync.m16n8k8 tf32, fp32 accumulate. Inputs rounded to tf32 at smem store.
// Smem layouts conflict-free for fragment loads:
//   As[m][36] (pad 4), Bs[k][136] (pad 8).
// ---------------------------------------------------------------------------
__global__ __launch_bounds__(256)
void gemm_tf32_kernel(const float* __restrict__ A,
                      const float* __restrict__ Bm,
                      const float* __restrict__ bias,
                      float* __restrict__ Cm,
                      int M, int N, int K) {
    __shared__ float As[128][36];   // [m][k] 18432 B
    __shared__ float Bs[32][136];   // [k][n] 17408 B

    const float* B = Bm + (size_t)blockIdx.z * K * N;
    float* Cp = Cm + (size_t)blockIdx.z * M * N;
    int m0 = blockIdx.y * 128;
    int n0 = blockIdx.x * 128;
    int tid = threadIdx.x;
    int lane = tid & 31;
    int warp = tid >> 5;
    int mw = (warp >> 1) * 32;   // warp m offset in tile
    int nw = (warp & 1) * 64;    // warp n offset in tile
    int lq = lane >> 2;          // 0..7
    int lr = lane & 3;           // 0..3

    float acc[2][8][4] = {};

    for (int k0 = 0; k0 < K; k0 += 32) {
        // Load A tile 128x32: thread -> (m = i>>3, k4 = i&7), float4 along k
#pragma unroll
        for (int it = 0; it < 4; it++) {
            int i = tid + it * 256;
            int m = i >> 3, k4 = i & 7;
            float4 v = *(const float4*)&A[(size_t)(m0 + m) * K + k0 + k4 * 4];
            v.x = to_tf32(v.x); v.y = to_tf32(v.y);
            v.z = to_tf32(v.z); v.w = to_tf32(v.w);
            *(float4*)&As[m][k4 * 4] = v;
        }
        // Load B tile 32x128: thread -> (k = i>>5, n4 = i&31), float4 along n
#pragma unroll
        for (int it = 0; it < 4; it++) {
            int i = tid + it * 256;
            int k = i >> 5, n4 = i & 31;
            float4 v = *(const float4*)&B[(size_t)(k0 + k) * N + n0 + n4 * 4];
            v.x = to_tf32(v.x); v.y = to_tf32(v.y);
            v.z = to_tf32(v.z); v.w = to_tf32(v.w);
            *(float4*)&Bs[k][n4 * 4] = v;
        }
        __syncthreads();

#pragma unroll
        for (int ks = 0; ks < 4; ks++) {
            int k8 = ks * 8;
            uint32_t a[2][4], b[8][2];
#pragma unroll
            for (int mi = 0; mi < 2; mi++) {
                int r = mw + 16 * mi + lq;
                a[mi][0] = __float_as_uint(As[r][k8 + lr]);
                a[mi][1] = __float_as_uint(As[r + 8][k8 + lr]);
                a[mi][2] = __float_as_uint(As[r][k8 + lr + 4]);
                a[mi][3] = __float_as_uint(As[r + 8][k8 + lr + 4]);
            }
#pragma unroll
            for (int ni = 0; ni < 8; ni++) {
                int c = nw + 8 * ni + lq;
                b[ni][0] = __float_as_uint(Bs[k8 + lr][c]);
                b[ni][1] = __float_as_uint(Bs[k8 + lr + 4][c]);
            }
#pragma unroll
            for (int mi = 0; mi < 2; mi++)
#pragma unroll
                for (int ni = 0; ni < 8; ni++)
                    mma_tf32(acc[mi][ni], a[mi], b[ni]);
        }
        __syncthreads();
    }

    // Epilogue: bias + store
#pragma unroll
    for (int mi = 0; mi < 2; mi++) {
        int row0 = m0 + mw + 16 * mi + lq;
        float bi0 = bias[row0];
        float bi1 = bias[row0 + 8];
#pragma unroll
        for (int ni = 0; ni < 8; ni++) {
            int col = n0 + nw + 8 * ni + 2 * lr;
            float* p0 = &Cp[(size_t)row0 * N + col];
            float* p1 = &Cp[(size_t)(row0 + 8) * N + col];
            p0[0] = acc[mi][ni][0] + bi0;
            p0[1] = acc[mi][ni][1] + bi0;
            p1[0] = acc[mi][ni][2] + bi1;
            p1[1] = acc[mi][ni][3] + bi1;
        }
    }
}

// ---------------------------------------------------------------------------
// Flash attention per (batch*head, 128-row t-tile). 256 threads. (unchanged)
// ---------------------------------------------------------------------------
__global__ __launch_bounds__(256)
void attn_kernel(const float* __restrict__ qkv,
                 float* __restrict__ aout) {
    extern __shared__ float sm[];
    float(*qs)[132] = (float(*)[132])sm;                          // [c=64][t=128]
    float(*ks)[68]  = (float(*)[68])(sm + 64 * 132);              // [c=64][s=64]
    float(*vsT)[68] = (float(*)[68])(sm + 64 * 132 + 64 * 68);    // [s=64][c=64]
    float(*Ps)[68]  = (float(*)[68])(sm + 64 * 132 + 2 * 64 * 68);// [t=128][s=64]

    int bh = blockIdx.y;
    int t0 = blockIdx.x * 128;
    int b = bh >> 3, h = bh & 7;
    const float* base = qkv + ((size_t)b * 1536 + h * 192) * 1024;
    int tid = threadIdx.x;
    int ty = tid >> 4;  // 0..15: t (8 rows each)
    int tx = tid & 15;  // 0..15: s (4 each) / c (4 each)

#pragma unroll
    for (int it = 0; it < 32; it++) {
        int i = tid + it * 256;
        int c = i >> 7, t = i & 127;
        qs[c][t] = base[c * 1024 + t0 + t] * 0.125f;
    }

    float mrow[8], lrow[8];
    float O[8][4] = {};
#pragma unroll
    for (int i = 0; i < 8; i++) { mrow[i] = -INFINITY; lrow[i] = 0.f; }
    __syncthreads();

    for (int s0 = 0; s0 < 1024; s0 += 64) {
#pragma unroll
        for (int it = 0; it < 16; it++) {
            int i = tid + it * 256;
            int c = i >> 6, s = i & 63;
            ks[c][s] = base[(64 + c) * 1024 + s0 + s];
        }
#pragma unroll
        for (int it = 0; it < 16; it++) {
            int i = tid + it * 256;
            int c = i >> 6, s = i & 63;
            vsT[s][c] = base[(128 + c) * 1024 + s0 + s];
        }
        __syncthreads();

        float S[8][4] = {};
#pragma unroll 8
        for (int c = 0; c < 64; c++) {
            float4 qa = *(const float4*)&qs[c][ty * 8];
            float4 qb = *(const float4*)&qs[c][ty * 8 + 4];
            float4 kb = *(const float4*)&ks[c][tx * 4];
            float av[8] = {qa.x, qa.y, qa.z, qa.w, qb.x, qb.y, qb.z, qb.w};
            float bv[4] = {kb.x, kb.y, kb.z, kb.w};
#pragma unroll
            for (int i = 0; i < 8; i++)
#pragma unroll
                for (int j = 0; j < 4; j++)
                    S[i][j] += av[i] * bv[j];
        }

#pragma unroll
        for (int i = 0; i < 8; i++) {
            float rmax = fmaxf(fmaxf(S[i][0], S[i][1]), fmaxf(S[i][2], S[i][3]));
#pragma unroll
            for (int o = 1; o < 16; o <<= 1)
                rmax = fmaxf(rmax, __shfl_xor_sync(0xffffffffu, rmax, o));
            float mn = fmaxf(mrow[i], rmax);
            float corr = __expf(mrow[i] - mn);
            float p[4];
            float psum = 0.f;
#pragma unroll
            for (int j = 0; j < 4; j++) {
                p[j] = __expf(S[i][j] - mn);
                psum += p[j];
            }
#pragma unroll
            for (int o = 1; o < 16; o <<= 1)
                psum += __shfl_xor_sync(0xffffffffu, psum, o);
            lrow[i] = lrow[i] * corr + psum;
            mrow[i] = mn;
#pragma unroll
            for (int j = 0; j < 4; j++) O[i][j] *= corr;
            *(float4*)&Ps[ty * 8 + i][tx * 4] = make_float4(p[0], p[1], p[2], p[3]);
        }
        __syncthreads();

#pragma unroll 8
        for (int s = 0; s < 64; s++) {
            float4 vb = *(const float4*)&vsT[s][tx * 4];
            float bv[4] = {vb.x, vb.y, vb.z, vb.w};
#pragma unroll
            for (int i = 0; i < 8; i++) {
                float p = Ps[ty * 8 + i][s];
#pragma unroll
                for (int j = 0; j < 4; j++)
                    O[i][j] += p * bv[j];
            }
        }
        __syncthreads();
    }

#pragma unroll
    for (int i = 0; i < 8; i++) {
        float inv = 1.0f / lrow[i];
#pragma unroll
        for (int j = 0; j < 4; j++)
            qs[tx * 4 + j][ty * 8 + i] = O[i][j] * inv;
    }
    __syncthreads();

    size_t obase = ((size_t)b * 512 + h * 64) * 1024 + t0;
#pragma unroll
    for (int it = 0; it < 8; it++) {
        int i = tid + it * 256;           // 64 rows x 32 float4
        int c = i >> 5, t4 = (i & 31) * 4;
        *(float4*)&aout[obase + (size_t)c * 1024 + t4] = *(const float4*)&qs[c][t4];
    }
}

// ---------------------------------------------------------------------------
// Launch
// ---------------------------------------------------------------------------
extern "C" void kernel_launch(void* const* d_in, const int* in_sizes, int n_in,
                              void* d_out, int out_size) {
    const float* x      = (const float*)d_in[0];
    const float* gn1_s  = (const float*)d_in[1];
    const float* gn1_b  = (const float*)d_in[2];
    const float* w_qkv  = (const float*)d_in[3];
    const float* b_qkv  = (const float*)d_in[4];
    const float* w_proj = (const float*)d_in[5];
    const float* b_proj = (const float*)d_in[6];
    const float* gn2_s  = (const float*)d_in[7];
    const float* gn2_b  = (const float*)d_in[8];
    float* out = (float*)d_out;

    float *hn, *qkv, *attn, *proj;
    cudaGetSymbolAddress((void**)&hn, g_hn);
    cudaGetSymbolAddress((void**)&qkv, g_qkv);
    cudaGetSymbolAddress((void**)&attn, g_attn);
    cudaGetSymbolAddress((void**)&proj, g_proj);

    const int ATTN_SMEM = (64 * 132 + 2 * 64 * 68 + 128 * 68) * 4;  // 103424 B
    cudaFuncSetAttribute(attn_kernel, cudaFuncAttributeMaxDynamicSharedMemorySize,
                         ATTN_SMEM);

    // 1) GroupNorm1
    gn_kernel<false><<<256, 256>>>(x, gn1_s, gn1_b, nullptr, hn);
    // 2) qkv = W_qkv @ hn + b  (batched: 1536 x 1024 x 512, 8 batches)
    gemm_tf32_kernel<<<dim3(8, 12, 8), 256>>>(w_qkv, hn, b_qkv, qkv, 1536, 1024, 512);
    // 3) flash attention per (bh, 128-row t-tile)
    attn_kernel<<<dim3(8, 64), 256, ATTN_SMEM>>>(qkv, attn);
    // 4) proj = W_proj @ a + b  (512 x 1024 x 512, 8 batches)
    gemm_tf32_kernel<<<dim3(8, 4, 8), 256>>>(w_proj, attn, b_proj, proj, 512, 1024, 512);
    // 5) GroupNorm2 + residual
    gn_kernel<true><<<256, 256>>>(proj, gn2_s, gn2_b, x, out);
}

// round 8
// speedup vs baseline: 3.5967x; 1.7245x over previous
#include <cuda_runtime.h>
#include <math.h>
#include <stdint.h>

// Problem constants
#define BATCH 8
#define CCH   512
#define NTOK  1024

// Scratch buffers (device globals — no allocation allowed)
__device__ float g_hn[BATCH * CCH * NTOK];        // GroupNorm1 output
__device__ float g_qkv[BATCH * 3 * CCH * NTOK];   // qkv conv output
__device__ float g_attn[BATCH * CCH * NTOK];      // attention output
__device__ float g_proj[BATCH * CCH * NTOK];      // proj conv output

// ---------------------------------------------------------------------------
// GroupNorm over 32 groups of 16 channels x 1024 spatial. One block per (b,g).
// ---------------------------------------------------------------------------
template <bool ADD_RES>
__global__ __launch_bounds__(256)
void gn_kernel(const float* __restrict__ x,
               const float* __restrict__ scale,
               const float* __restrict__ bias,
               const float* __restrict__ resid,
               float* __restrict__ out) {
    __shared__ float s_sum[256];
    __shared__ float s_sq[256];
    int blk = blockIdx.x;           // b*32 + g
    int g = blk & 31;
    size_t base = (size_t)blk * 16 * 1024;
    int tid = threadIdx.x;

    float sum = 0.f, sq = 0.f;
    for (int i = tid; i < 16384; i += 256) {
        float v = x[base + i];
        sum += v;
        sq += v * v;
    }
    s_sum[tid] = sum;
    s_sq[tid] = sq;
    __syncthreads();
    for (int off = 128; off; off >>= 1) {
        if (tid < off) {
            s_sum[tid] += s_sum[tid + off];
            s_sq[tid] += s_sq[tid + off];
        }
        __syncthreads();
    }
    float mean = s_sum[0] * (1.0f / 16384.0f);
    float var = s_sq[0] * (1.0f / 16384.0f) - mean * mean;
    float rstd = rsqrtf(var + 1e-5f);

    for (int i = tid; i < 16384; i += 256) {
        int c = g * 16 + (i >> 10);
        float v = (x[base + i] - mean) * rstd * scale[c] + bias[c];
        out[base + i] = ADD_RES ? resid[base + i] + v : v;
    }
}

// ---------------------------------------------------------------------------
// tf32 helpers
// ---------------------------------------------------------------------------
__device__ __forceinline__ float to_tf32(float x) {
    float y;
    asm("cvt.rna.tf32.f32 %0, %1;" : "=f"(y) : "f"(x));
    return y;
}

__device__ __forceinline__ void mma_tf32(float* c, const uint32_t* a, const uint32_t* b) {
    asm volatile(
        "mma.sync.aligned.m16n8k8.row.col.f32.tf32.tf32.f32 "
        "{%0,%1,%2,%3}, {%4,%5,%6,%7}, {%8,%9}, {%0,%1,%2,%3};"
        : "+f"(c[0]), "+f"(c[1]), "+f"(c[2]), "+f"(c[3])
        : "r"(a[0]), "r"(a[1]), "r"(a[2]), "r"(a[3]), "r"(b[0]), "r"(b[1]));
}

// ---------------------------------------------------------------------------
// Batched tf32 tensor-core GEMM + bias (unchanged from R6):
//   C[z][m][n] = sum_k A[m][k] * B[z][k][n] + bias[m]
// ---------------------------------------------------------------------------
__global__ __launch_bounds__(256)
void gemm_tf32_kernel(const float* __restrict__ A,
                      const float* __restrict__ Bm,
                      const float* __restrict__ bias,
                      float* __restrict__ Cm,
                      int M, int N, int K) {
    __shared__ float As[128][36];   // [m][k]
    __shared__ float Bs[32][136];   // [k][n]

    const float* B = Bm + (size_t)blockIdx.z * K * N;
    float* Cp = Cm + (size_t)blockIdx.z * M * N;
    int m0 = blockIdx.y * 128;
    int n0 = blockIdx.x * 128;
    int tid = threadIdx.x;
    int lane = tid & 31;
    int warp = tid >> 5;
    int mw = (warp >> 1) * 32;
    int nw = (warp & 1) * 64;
    int lq = lane >> 2;
    int lr = lane & 3;

    float acc[2][8][4] = {};

    for (int k0 = 0; k0 < K; k0 += 32) {
#pragma unroll
        for (int it = 0; it < 4; it++) {
            int i = tid + it * 256;
            int m = i >> 3, k4 = i & 7;
            float4 v = *(const float4*)&A[(size_t)(m0 + m) * K + k0 + k4 * 4];
            v.x = to_tf32(v.x); v.y = to_tf32(v.y);
            v.z = to_tf32(v.z); v.w = to_tf32(v.w);
            *(float4*)&As[m][k4 * 4] = v;
        }
#pragma unroll
        for (int it = 0; it < 4; it++) {
            int i = tid + it * 256;
            int k = i >> 5, n4 = i & 31;
            float4 v = *(const float4*)&B[(size_t)(k0 + k) * N + n0 + n4 * 4];
            v.x = to_tf32(v.x); v.y = to_tf32(v.y);
            v.z = to_tf32(v.z); v.w = to_tf32(v.w);
            *(float4*)&Bs[k][n4 * 4] = v;
        }
        __syncthreads();

#pragma unroll
        for (int ks = 0; ks < 4; ks++) {
            int k8 = ks * 8;
            uint32_t a[2][4], b[8][2];
#pragma unroll
            for (int mi = 0; mi < 2; mi++) {
                int r = mw + 16 * mi + lq;
                a[mi][0] = __float_as_uint(As[r][k8 + lr]);
                a[mi][1] = __float_as_uint(As[r + 8][k8 + lr]);
                a[mi][2] = __float_as_uint(As[r][k8 + lr + 4]);
                a[mi][3] = __float_as_uint(As[r + 8][k8 + lr + 4]);
            }
#pragma unroll
            for (int ni = 0; ni < 8; ni++) {
                int c = nw + 8 * ni + lq;
                b[ni][0] = __float_as_uint(Bs[k8 + lr][c]);
                b[ni][1] = __float_as_uint(Bs[k8 + lr + 4][c]);
            }
#pragma unroll
            for (int mi = 0; mi < 2; mi++)
#pragma unroll
                for (int ni = 0; ni < 8; ni++)
                    mma_tf32(acc[mi][ni], a[mi], b[ni]);
        }
        __syncthreads();
    }

#pragma unroll
    for (int mi = 0; mi < 2; mi++) {
        int row0 = m0 + mw + 16 * mi + lq;
        float bi0 = bias[row0];
        float bi1 = bias[row0 + 8];
#pragma unroll
        for (int ni = 0; ni < 8; ni++) {
            int col = n0 + nw + 8 * ni + 2 * lr;
            float* p0 = &Cp[(size_t)row0 * N + col];
            float* p1 = &Cp[(size_t)(row0 + 8) * N + col];
            p0[0] = acc[mi][ni][0] + bi0;
            p0[1] = acc[mi][ni][1] + bi0;
            p1[0] = acc[mi][ni][2] + bi1;
            p1[1] = acc[mi][ni][3] + bi1;
        }
    }
}

// ---------------------------------------------------------------------------
// Tensor-core flash attention. Block = (bh, 128-row t-tile), 8 warps.
// Warp tile: 16 t-rows x full 64-wide s (softmax stays in-warp).
// QK: A = qs[t][c] (stride 68), B = ks[c][s] (stride 72).
// PV: A = Ps[t][s] (stride 68), B = vsT[s][c] (stride 72).
// scale^2 = 0.125 folded into q. All operands tf32-rounded at smem store.
// ---------------------------------------------------------------------------
__global__ __launch_bounds__(256)
void attn_tc_kernel(const float* __restrict__ qkv,
                    float* __restrict__ aout) {
    extern __shared__ float sm[];
    float(*qs)[68]  = (float(*)[68])sm;                         // [t=128][c=64]
    float(*ks)[72]  = (float(*)[72])(sm + 128 * 68);            // [c=64][s=64]
    float(*vsT)[72] = (float(*)[72])(sm + 128 * 68 + 64 * 72);  // [s=64][c=64]
    float(*Ps)[68]  = (float(*)[68])(sm + 128 * 68 + 2 * 64 * 72); // [t=128][s=64]

    int bh = blockIdx.y;
    int t0 = blockIdx.x * 128;
    int b = bh >> 3, h = bh & 7;
    const float* base = qkv + ((size_t)b * 1536 + h * 192) * 1024;
    int tid = threadIdx.x;
    int lane = tid & 31;
    int warp = tid >> 5;
    int lq = lane >> 2;   // 0..7
    int lr = lane & 3;    // 0..3
    int rw = warp * 16;   // warp's t-row base
    int r0 = rw + lq, r1 = rw + lq + 8;

    // Load Q -> qs[t][c], fold scale^2 = 0.125, round to tf32.
#pragma unroll
    for (int it = 0; it < 32; it++) {
        int i = tid + it * 256;
        int c = i >> 7, t = i & 127;
        qs[t][c] = to_tf32(base[c * 1024 + t0 + t] * 0.125f);
    }

    float m0v = -INFINITY, m1v = -INFINITY, l0 = 0.f, l1 = 0.f;
    float accO[8][4] = {};
    __syncthreads();

    for (int s0 = 0; s0 < 1024; s0 += 64) {
        // K tile -> ks[c][s] (natural, float4, conflict-free)
#pragma unroll
        for (int it = 0; it < 4; it++) {
            int i = tid + it * 256;
            int c = i >> 4, s4 = (i & 15) * 4;
            float4 v = *(const float4*)&base[(64 + c) * 1024 + s0 + s4];
            v.x = to_tf32(v.x); v.y = to_tf32(v.y);
            v.z = to_tf32(v.z); v.w = to_tf32(v.w);
            *(float4*)&ks[c][s4] = v;
        }
        // V tile -> vsT[s][c] (transposed scalar stores)
#pragma unroll
        for (int it = 0; it < 16; it++) {
            int i = tid + it * 256;
            int c = i >> 6, s = i & 63;
            vsT[s][c] = to_tf32(base[(128 + c) * 1024 + s0 + s]);
        }
        __syncthreads();

        // S = Q^T K : warp tile 16 x 64
        float accS[8][4] = {};
#pragma unroll
        for (int ks8 = 0; ks8 < 8; ks8++) {
            int k8 = ks8 * 8;
            uint32_t a[4];
            a[0] = __float_as_uint(qs[r0][k8 + lr]);
            a[1] = __float_as_uint(qs[r1][k8 + lr]);
            a[2] = __float_as_uint(qs[r0][k8 + lr + 4]);
            a[3] = __float_as_uint(qs[r1][k8 + lr + 4]);
#pragma unroll
            for (int ni = 0; ni < 8; ni++) {
                uint32_t bb[2];
                bb[0] = __float_as_uint(ks[k8 + lr][8 * ni + lq]);
                bb[1] = __float_as_uint(ks[k8 + lr + 4][8 * ni + lq]);
                mma_tf32(accS[ni], a, bb);
            }
        }

        // Online softmax: rows r0 (c0,c1) and r1 (c2,c3); row spread over 4 lanes.
        float rm0 = -INFINITY, rm1 = -INFINITY;
#pragma unroll
        for (int ni = 0; ni < 8; ni++) {
            rm0 = fmaxf(rm0, fmaxf(accS[ni][0], accS[ni][1]));
            rm1 = fmaxf(rm1, fmaxf(accS[ni][2], accS[ni][3]));
        }
        rm0 = fmaxf(rm0, __shfl_xor_sync(0xffffffffu, rm0, 1));
        rm0 = fmaxf(rm0, __shfl_xor_sync(0xffffffffu, rm0, 2));
        rm1 = fmaxf(rm1, __shfl_xor_sync(0xffffffffu, rm1, 1));
        rm1 = fmaxf(rm1, __shfl_xor_sync(0xffffffffu, rm1, 2));
        float mn0 = fmaxf(m0v, rm0), mn1 = fmaxf(m1v, rm1);
        float corr0 = __expf(m0v - mn0), corr1 = __expf(m1v - mn1);
        float ps0 = 0.f, ps1 = 0.f;
#pragma unroll
        for (int ni = 0; ni < 8; ni++) {
            float p00 = __expf(accS[ni][0] - mn0);
            float p01 = __expf(accS[ni][1] - mn0);
            float p10 = __expf(accS[ni][2] - mn1);
            float p11 = __expf(accS[ni][3] - mn1);
            ps0 += p00 + p01;
            ps1 += p10 + p11;
            int c = 8 * ni + 2 * lr;
            Ps[r0][c]     = to_tf32(p00);
            Ps[r0][c + 1] = to_tf32(p01);
            Ps[r1][c]     = to_tf32(p10);
            Ps[r1][c + 1] = to_tf32(p11);
        }
        ps0 += __shfl_xor_sync(0xffffffffu, ps0, 1);
        ps0 += __shfl_xor_sync(0xffffffffu, ps0, 2);
        ps1 += __shfl_xor_sync(0xffffffffu, ps1, 1);
        ps1 += __shfl_xor_sync(0xffffffffu, ps1, 2);
        l0 = l0 * corr0 + ps0;
        l1 = l1 * corr1 + ps1;
        m0v = mn0; m1v = mn1;
#pragma unroll
        for (int ni = 0; ni < 8; ni++) {
            accO[ni][0] *= corr0; accO[ni][1] *= corr0;
            accO[ni][2] *= corr1; accO[ni][3] *= corr1;
        }
        __syncwarp();  // Ps visible within the warp (warp reads only its own rows)

        // O += P V : warp tile 16 x 64, contraction over s
#pragma unroll
        for (int ks8 = 0; ks8 < 8; ks8++) {
            int k8 = ks8 * 8;
            uint32_t a[4];
            a[0] = __float_as_uint(Ps[r0][k8 + lr]);
            a[1] = __float_as_uint(Ps[r1][k8 + lr]);
            a[2] = __float_as_uint(Ps[r0][k8 + lr + 4]);
            a[3] = __float_as_uint(Ps[r1][k8 + lr + 4]);
#pragma unroll
            for (int ni = 0; ni < 8; ni++) {
                uint32_t bb[2];
                bb[0] = __float_as_uint(vsT[k8 + lr][8 * ni + lq]);
                bb[1] = __float_as_uint(vsT[k8 + lr + 4][8 * ni + lq]);
                mma_tf32(accO[ni], a, bb);
            }
        }
        __syncthreads();  // all warps done with ks/vsT before next-iter overwrite
    }

    // Epilogue: normalize, stage transposed [c][t] (reuses qs region), store.
    float inv0 = 1.0f / l0, inv1 = 1.0f / l1;
    float(*outS)[132] = (float(*)[132])sm;   // 64 x 132 fits in qs region
#pragma unroll
    for (int ni = 0; ni < 8; ni++) {
        int c = 8 * ni + 2 * lr;
        outS[c][r0]     = accO[ni][0] * inv0;
        outS[c + 1][r0] = accO[ni][1] * inv0;
        outS[c][r1]     = accO[ni][2] * inv1;
        outS[c + 1][r1] = accO[ni][3] * inv1;
    }
    __syncthreads();

    size_t obase = ((size_t)b * 512 + h * 64) * 1024 + t0;
#pragma unroll
    for (int it = 0; it < 8; it++) {
        int i = tid + it * 256;           // 64 rows x 32 float4
        int c = i >> 5, t4 = (i & 31) * 4;
        *(float4*)&aout[obase + (size_t)c * 1024 + t4] = *(const float4*)&outS[c][t4];
    }
}

// ---------------------------------------------------------------------------
// Launch
// ---------------------------------------------------------------------------
extern "C" void kernel_launch(void* const* d_in, const int* in_sizes, int n_in,
                              void* d_out, int out_size) {
    const float* x      = (const float*)d_in[0];
    const float* gn1_s  = (const float*)d_in[1];
    const float* gn1_b  = (const float*)d_in[2];
    const float* w_qkv  = (const float*)d_in[3];
    const float* b_qkv  = (const float*)d_in[4];
    const float* w_proj = (const float*)d_in[5];
    const float* b_proj = (const float*)d_in[6];
    const float* gn2_s  = (const float*)d_in[7];
    const float* gn2_b  = (const float*)d_in[8];
    float* out = (float*)d_out;

    float *hn, *qkv, *attn, *proj;
    cudaGetSymbolAddress((void**)&hn, g_hn);
    cudaGetSymbolAddress((void**)&qkv, g_qkv);
    cudaGetSymbolAddress((void**)&attn, g_attn);
    cudaGetSymbolAddress((void**)&proj, g_proj);

    const int ATTN_SMEM = (128 * 68 + 2 * 64 * 72 + 128 * 68) * 4;  // 106496 B
    cudaFuncSetAttribute(attn_tc_kernel, cudaFuncAttributeMaxDynamicSharedMemorySize,
                         ATTN_SMEM);

    // 1) GroupNorm1
    gn_kernel<false><<<256, 256>>>(x, gn1_s, gn1_b, nullptr, hn);
    // 2) qkv = W_qkv @ hn + b  (batched: 1536 x 1024 x 512, 8 batches)
    gemm_tf32_kernel<<<dim3(8, 12, 8), 256>>>(w_qkv, hn, b_qkv, qkv, 1536, 1024, 512);
    // 3) tensor-core flash attention per (bh, 128-row t-tile)
    attn_tc_kernel<<<dim3(8, 64), 256, ATTN_SMEM>>>(qkv, attn);
    // 4) proj = W_proj @ a + b  (512 x 1024 x 512, 8 batches)
    gemm_tf32_kernel<<<dim3(8, 4, 8), 256>>>(w_proj, attn, b_proj, proj, 512, 1024, 512);
    // 5) GroupNorm2 + residual
    gn_kernel<true><<<256, 256>>>(proj, gn2_s, gn2_b, x, out);
}